// round 3
// baseline (speedup 1.0000x reference)
#include <cuda_runtime.h>
#include <math.h>

#define BB 2
#define SS 2048
#define DD 2048
#define NH 16
#define DH 128
#define RR 64
#define MM (BB*SS)   /* 4096 */

// ---------------- scratch (device globals; no allocation) ----------------
static __device__ float g_wq[DD*RR];
static __device__ float g_wk[DD*RR];
static __device__ float g_wv[DD*RR];
static __device__ float g_wo[DD*RR];
static __device__ float g_resq[MM*RR];
static __device__ float g_resk[MM*RR];
static __device__ float g_resv[MM*RR];
static __device__ float g_q[(size_t)MM*DD];
static __device__ float g_k[(size_t)MM*DD];
static __device__ float g_v[(size_t)MM*DD];
static __device__ float g_ao[(size_t)MM*DD];

// ---------------- w = amp * cos(phase) ----------------
__global__ void wcos_kernel(const float* __restrict__ amp,
                            const float* __restrict__ phase,
                            float* __restrict__ w) {
    int i = blockIdx.x * 256 + threadIdx.x;
    w[i] = amp[i] * cosf(phase[i]);
}

// ---------------- fused QKV resonance GEMM ----------------
// res_x[m][n] = sum_k X[m][k] * Bas_x[n][k] for x in {q,k,v}
// M=4096, N=64 (full tile), K=2048. One CTA per 64-row tile of X.
// X tile loaded ONCE per k-step; reused against all three basis tiles.
__global__ __launch_bounds__(256) void gemm_res_qkv(const float* __restrict__ X,
                                                    const float* __restrict__ BasQ,
                                                    const float* __restrict__ BasK,
                                                    const float* __restrict__ BasV,
                                                    float* __restrict__ outQ,
                                                    float* __restrict__ outK,
                                                    float* __restrict__ outV) {
    __shared__ float As[64][36];
    __shared__ float Bq[64][36];
    __shared__ float Bk[64][36];
    __shared__ float Bv[64][36];
    int tid = threadIdx.x;
    int tx = tid & 15, ty = tid >> 4;
    int m0 = blockIdx.x * 64;

    float aq[4][4] = {}, ak[4][4] = {}, av[4][4] = {};

    for (int kk = 0; kk < DD; kk += 32) {
        #pragma unroll
        for (int t = tid; t < 512; t += 256) {
            int r = t >> 3, c4 = t & 7;
            float4 v = *reinterpret_cast<const float4*>(&X[(size_t)(m0 + r) * DD + kk + c4 * 4]);
            As[r][c4*4+0] = v.x; As[r][c4*4+1] = v.y; As[r][c4*4+2] = v.z; As[r][c4*4+3] = v.w;
            float4 q4 = *reinterpret_cast<const float4*>(&BasQ[(size_t)r * DD + kk + c4 * 4]);
            Bq[r][c4*4+0] = q4.x; Bq[r][c4*4+1] = q4.y; Bq[r][c4*4+2] = q4.z; Bq[r][c4*4+3] = q4.w;
            float4 k4 = *reinterpret_cast<const float4*>(&BasK[(size_t)r * DD + kk + c4 * 4]);
            Bk[r][c4*4+0] = k4.x; Bk[r][c4*4+1] = k4.y; Bk[r][c4*4+2] = k4.z; Bk[r][c4*4+3] = k4.w;
            float4 v4 = *reinterpret_cast<const float4*>(&BasV[(size_t)r * DD + kk + c4 * 4]);
            Bv[r][c4*4+0] = v4.x; Bv[r][c4*4+1] = v4.y; Bv[r][c4*4+2] = v4.z; Bv[r][c4*4+3] = v4.w;
        }
        __syncthreads();
        #pragma unroll
        for (int k = 0; k < 32; k += 4) {
            float4 a[4];
            #pragma unroll
            for (int i = 0; i < 4; i++) a[i] = *reinterpret_cast<const float4*>(&As[ty*4+i][k]);
            float4 b[4];
            #pragma unroll
            for (int j = 0; j < 4; j++) b[j] = *reinterpret_cast<const float4*>(&Bq[tx*4+j][k]);
            #pragma unroll
            for (int i = 0; i < 4; i++)
                #pragma unroll
                for (int j = 0; j < 4; j++)
                    aq[i][j] += a[i].x*b[j].x + a[i].y*b[j].y + a[i].z*b[j].z + a[i].w*b[j].w;
            #pragma unroll
            for (int j = 0; j < 4; j++) b[j] = *reinterpret_cast<const float4*>(&Bk[tx*4+j][k]);
            #pragma unroll
            for (int i = 0; i < 4; i++)
                #pragma unroll
                for (int j = 0; j < 4; j++)
                    ak[i][j] += a[i].x*b[j].x + a[i].y*b[j].y + a[i].z*b[j].z + a[i].w*b[j].w;
            #pragma unroll
            for (int j = 0; j < 4; j++) b[j] = *reinterpret_cast<const float4*>(&Bv[tx*4+j][k]);
            #pragma unroll
            for (int i = 0; i < 4; i++)
                #pragma unroll
                for (int j = 0; j < 4; j++)
                    av[i][j] += a[i].x*b[j].x + a[i].y*b[j].y + a[i].z*b[j].z + a[i].w*b[j].w;
        }
        __syncthreads();
    }
    #pragma unroll
    for (int i = 0; i < 4; i++)
        #pragma unroll
        for (int j = 0; j < 4; j++) {
            size_t o = (size_t)(m0 + ty*4 + i) * RR + tx*4 + j;
            outQ[o] = aq[i][j];
            outK[o] = ak[i][j];
            outV[o] = av[i][j];
        }
}

// ---------------- single resonance GEMM (for O projection) ----------------
__global__ __launch_bounds__(256) void gemm_res(const float* __restrict__ X,
                                                const float* __restrict__ Bas,
                                                float* __restrict__ out) {
    __shared__ float As[64][36];
    __shared__ float Bs[64][36];
    int tid = threadIdx.x;
    int tx = tid & 15, ty = tid >> 4;
    int m0 = blockIdx.x * 64;

    float acc[4][4] = {};

    for (int kk = 0; kk < DD; kk += 32) {
        #pragma unroll
        for (int t = tid; t < 512; t += 256) {
            int r = t >> 3, c4 = t & 7;
            float4 v = *reinterpret_cast<const float4*>(&X[(size_t)(m0 + r) * DD + kk + c4 * 4]);
            As[r][c4*4+0] = v.x; As[r][c4*4+1] = v.y; As[r][c4*4+2] = v.z; As[r][c4*4+3] = v.w;
        }
        #pragma unroll
        for (int t = tid; t < 512; t += 256) {
            int r = t >> 3, c4 = t & 7;
            float4 v = *reinterpret_cast<const float4*>(&Bas[(size_t)r * DD + kk + c4 * 4]);
            Bs[r][c4*4+0] = v.x; Bs[r][c4*4+1] = v.y; Bs[r][c4*4+2] = v.z; Bs[r][c4*4+3] = v.w;
        }
        __syncthreads();
        #pragma unroll
        for (int k = 0; k < 32; k += 4) {
            float4 a[4], b[4];
            #pragma unroll
            for (int i = 0; i < 4; i++) a[i] = *reinterpret_cast<const float4*>(&As[ty*4+i][k]);
            #pragma unroll
            for (int j = 0; j < 4; j++) b[j] = *reinterpret_cast<const float4*>(&Bs[tx*4+j][k]);
            #pragma unroll
            for (int i = 0; i < 4; i++)
                #pragma unroll
                for (int j = 0; j < 4; j++)
                    acc[i][j] += a[i].x*b[j].x + a[i].y*b[j].y + a[i].z*b[j].z + a[i].w*b[j].w;
        }
        __syncthreads();
    }
    #pragma unroll
    for (int i = 0; i < 4; i++)
        #pragma unroll
        for (int j = 0; j < 4; j++)
            out[(size_t)(m0 + ty*4 + i) * RR + tx*4 + j] = acc[i][j];
}

// ---------------- expand GEMM: out[m][n] = sum_h res[m][h] * w[n][h] ----------------
// M=4096, N=2048, K=64 (single pass). Grid (64, 32).
__global__ __launch_bounds__(256) void gemm_expand(const float* __restrict__ res,
                                                   const float* __restrict__ w,
                                                   float* __restrict__ out) {
    __shared__ float As[64][68];
    __shared__ float Bs[64][68];
    int tid = threadIdx.x;
    int tx = tid & 15, ty = tid >> 4;
    int m0 = blockIdx.x * 64;
    int n0 = blockIdx.y * 64;

    #pragma unroll
    for (int t = tid; t < 1024; t += 256) {
        int r = t >> 4, c4 = t & 15;
        float4 v = *reinterpret_cast<const float4*>(&res[(size_t)(m0 + r) * RR + c4 * 4]);
        As[r][c4*4+0] = v.x; As[r][c4*4+1] = v.y; As[r][c4*4+2] = v.z; As[r][c4*4+3] = v.w;
    }
    #pragma unroll
    for (int t = tid; t < 1024; t += 256) {
        int r = t >> 4, c4 = t & 15;
        float4 v = *reinterpret_cast<const float4*>(&w[(size_t)(n0 + r) * RR + c4 * 4]);
        Bs[r][c4*4+0] = v.x; Bs[r][c4*4+1] = v.y; Bs[r][c4*4+2] = v.z; Bs[r][c4*4+3] = v.w;
    }
    __syncthreads();

    float acc[4][4] = {};
    #pragma unroll
    for (int k = 0; k < 64; k += 4) {
        float4 a[4], b[4];
        #pragma unroll
        for (int i = 0; i < 4; i++) a[i] = *reinterpret_cast<const float4*>(&As[ty*4+i][k]);
        #pragma unroll
        for (int j = 0; j < 4; j++) b[j] = *reinterpret_cast<const float4*>(&Bs[tx*4+j][k]);
        #pragma unroll
        for (int i = 0; i < 4; i++)
            #pragma unroll
            for (int j = 0; j < 4; j++)
                acc[i][j] += a[i].x*b[j].x + a[i].y*b[j].y + a[i].z*b[j].z + a[i].w*b[j].w;
    }
    #pragma unroll
    for (int i = 0; i < 4; i++)
        #pragma unroll
        for (int j = 0; j < 4; j++)
            out[(size_t)(m0 + ty*4 + i) * DD + n0 + tx*4 + j] = acc[i][j];
}

// ---------------- flash attention (fp32, online softmax) ----------------
// grid (32 qtiles, 16 heads, 2 batch), 256 threads, ~116KB dyn smem.
#define QROW 132
#define PROW 68
#define SM_Q 0
#define SM_K (64*QROW)
#define SM_V (2*64*QROW)
#define SM_P (3*64*QROW)
#define ATTN_SMEM_BYTES ((3*64*QROW + 64*PROW) * 4)

__global__ __launch_bounds__(256) void attn_kernel() {
    extern __shared__ float sm[];
    float* Qs = sm + SM_Q;
    float* Ks = sm + SM_K;
    float* Vs = sm + SM_V;
    float* Ps = sm + SM_P;

    int tid = threadIdx.x;
    int tx = tid & 15, ty = tid >> 4;
    int qt = blockIdx.x;
    int h  = blockIdx.y;
    int bz = blockIdx.z;
    const float scale = 0.08838834764831845f;  // 1/sqrt(128)

    const float* qbase = g_q + (size_t)(bz * SS + qt * 64) * DD + h * DH;

    #pragma unroll
    for (int t = tid; t < 2048; t += 256) {
        int r = t >> 5, c4 = t & 31;
        float4 v = *reinterpret_cast<const float4*>(&qbase[(size_t)r * DD + c4 * 4]);
        *reinterpret_cast<float4*>(&Qs[r * QROW + c4 * 4]) = v;
    }

    float m[4], l[4], O[4][8];
    #pragma unroll
    for (int i = 0; i < 4; i++) {
        m[i] = -INFINITY; l[i] = 0.f;
        #pragma unroll
        for (int c = 0; c < 8; c++) O[i][c] = 0.f;
    }

    for (int jt = 0; jt < 32; jt++) {
        __syncthreads();   // previous PV done before overwriting K/V/P
        const float* kbase = g_k + (size_t)(bz * SS + jt * 64) * DD + h * DH;
        const float* vbase = g_v + (size_t)(bz * SS + jt * 64) * DD + h * DH;
        #pragma unroll
        for (int t = tid; t < 2048; t += 256) {
            int r = t >> 5, c4 = t & 31;
            float4 kv = *reinterpret_cast<const float4*>(&kbase[(size_t)r * DD + c4 * 4]);
            float4 vv = *reinterpret_cast<const float4*>(&vbase[(size_t)r * DD + c4 * 4]);
            *reinterpret_cast<float4*>(&Ks[r * QROW + c4 * 4]) = kv;
            *reinterpret_cast<float4*>(&Vs[r * QROW + c4 * 4]) = vv;
        }
        __syncthreads();

        // S = Q @ K^T (4x4 per thread)
        float s[4][4] = {};
        const float* qrow = &Qs[(ty * 4) * QROW];
        const float* krow = &Ks[(tx * 4) * QROW];
        #pragma unroll 4
        for (int d = 0; d < DH; d += 4) {
            float4 a[4], b[4];
            #pragma unroll
            for (int i = 0; i < 4; i++) a[i] = *reinterpret_cast<const float4*>(&qrow[i * QROW + d]);
            #pragma unroll
            for (int j = 0; j < 4; j++) b[j] = *reinterpret_cast<const float4*>(&krow[j * QROW + d]);
            #pragma unroll
            for (int i = 0; i < 4; i++)
                #pragma unroll
                for (int j = 0; j < 4; j++)
                    s[i][j] += a[i].x*b[j].x + a[i].y*b[j].y + a[i].z*b[j].z + a[i].w*b[j].w;
        }

        // online softmax per row (reduce across 16 lanes sharing the row)
        #pragma unroll
        for (int i = 0; i < 4; i++) {
            float mx = s[i][0];
            #pragma unroll
            for (int j = 1; j < 4; j++) mx = fmaxf(mx, s[i][j]);
            mx *= scale;
            #pragma unroll
            for (int off = 8; off >= 1; off >>= 1)
                mx = fmaxf(mx, __shfl_xor_sync(0xffffffffu, mx, off));
            float mnew = fmaxf(m[i], mx);
            float p[4], psum = 0.f;
            #pragma unroll
            for (int j = 0; j < 4; j++) {
                p[j] = __expf(s[i][j] * scale - mnew);
                psum += p[j];
            }
            #pragma unroll
            for (int off = 8; off >= 1; off >>= 1)
                psum += __shfl_xor_sync(0xffffffffu, psum, off);
            float alpha = __expf(m[i] - mnew);
            l[i] = l[i] * alpha + psum;
            m[i] = mnew;
            #pragma unroll
            for (int c = 0; c < 8; c++) O[i][c] *= alpha;
            #pragma unroll
            for (int j = 0; j < 4; j++)
                Ps[(ty * 4 + i) * PROW + tx * 4 + j] = p[j];
        }
        __syncthreads();

        // O += P @ V
        const float* prow = &Ps[(ty * 4) * PROW];
        #pragma unroll 2
        for (int k0 = 0; k0 < 64; k0 += 4) {
            float4 p[4];
            #pragma unroll
            for (int i = 0; i < 4; i++) p[i] = *reinterpret_cast<const float4*>(&prow[i * PROW + k0]);
            #pragma unroll
            for (int kk = 0; kk < 4; kk++) {
                int k = k0 + kk;
                float pv[4];
                pv[0] = (kk==0)?p[0].x:((kk==1)?p[0].y:((kk==2)?p[0].z:p[0].w));
                pv[1] = (kk==0)?p[1].x:((kk==1)?p[1].y:((kk==2)?p[1].z:p[1].w));
                pv[2] = (kk==0)?p[2].x:((kk==1)?p[2].y:((kk==2)?p[2].z:p[2].w));
                pv[3] = (kk==0)?p[3].x:((kk==1)?p[3].y:((kk==2)?p[3].z:p[3].w));
                #pragma unroll
                for (int cc = 0; cc < 8; cc++) {
                    float v = Vs[k * QROW + cc * 16 + tx];
                    O[0][cc] += pv[0] * v;
                    O[1][cc] += pv[1] * v;
                    O[2][cc] += pv[2] * v;
                    O[3][cc] += pv[3] * v;
                }
            }
        }
    }

    // epilogue: normalize and write to g_ao (layout b, s, h*128 + d)
    #pragma unroll
    for (int i = 0; i < 4; i++) {
        float inv = 1.0f / l[i];
        size_t row = (size_t)(bz * SS + qt * 64 + ty * 4 + i);
        #pragma unroll
        for (int cc = 0; cc < 8; cc++) {
            g_ao[row * DD + h * DH + cc * 16 + tx] = O[i][cc] * inv;
        }
    }
}

// ---------------- launch ----------------
extern "C" void kernel_launch(void* const* d_in, const int* in_sizes, int n_in,
                              void* d_out, int out_size) {
    const float* x       = (const float*)d_in[0];
    const float* basis_q = (const float*)d_in[1];
    const float* phase_q = (const float*)d_in[2];
    const float* amp_q   = (const float*)d_in[3];
    const float* basis_k = (const float*)d_in[4];
    const float* phase_k = (const float*)d_in[5];
    const float* amp_k   = (const float*)d_in[6];
    const float* basis_v = (const float*)d_in[7];
    const float* phase_v = (const float*)d_in[8];
    const float* amp_v   = (const float*)d_in[9];
    const float* basis_o = (const float*)d_in[10];
    const float* phase_o = (const float*)d_in[11];
    const float* amp_o   = (const float*)d_in[12];
    float* out = (float*)d_out;

    float *wq, *wk, *wv, *wo, *resq, *resk, *resv, *q, *k, *v, *ao;
    cudaGetSymbolAddress((void**)&wq, g_wq);
    cudaGetSymbolAddress((void**)&wk, g_wk);
    cudaGetSymbolAddress((void**)&wv, g_wv);
    cudaGetSymbolAddress((void**)&wo, g_wo);
    cudaGetSymbolAddress((void**)&resq, g_resq);
    cudaGetSymbolAddress((void**)&resk, g_resk);
    cudaGetSymbolAddress((void**)&resv, g_resv);
    cudaGetSymbolAddress((void**)&q, g_q);
    cudaGetSymbolAddress((void**)&k, g_k);
    cudaGetSymbolAddress((void**)&v, g_v);
    cudaGetSymbolAddress((void**)&ao, g_ao);

    cudaFuncSetAttribute(attn_kernel, cudaFuncAttributeMaxDynamicSharedMemorySize,
                         ATTN_SMEM_BYTES);

    // weights
    wcos_kernel<<<512, 256>>>(amp_q, phase_q, wq);
    wcos_kernel<<<512, 256>>>(amp_k, phase_k, wk);
    wcos_kernel<<<512, 256>>>(amp_v, phase_v, wv);
    wcos_kernel<<<512, 256>>>(amp_o, phase_o, wo);

    // fused q/k/v resonance, then expansions
    gemm_res_qkv<<<64, 256>>>(x, basis_q, basis_k, basis_v, resq, resk, resv);
    gemm_expand<<<dim3(64, 32), 256>>>(resq, wq, q);
    gemm_expand<<<dim3(64, 32), 256>>>(resk, wk, k);
    gemm_expand<<<dim3(64, 32), 256>>>(resv, wv, v);

    // attention
    attn_kernel<<<dim3(32, 16, 2), 256, ATTN_SMEM_BYTES>>>();

    // output projection
    gemm_res<<<64, 256>>>(ao, basis_o, resq);
    gemm_expand<<<dim3(64, 32), 256>>>(resq, wo, out);
}

// round 5
// speedup vs baseline: 1.6896x; 1.6896x over previous
#include <cuda_runtime.h>
#include <math.h>
#include <stdint.h>

#define BB 2
#define SS 2048
#define DD 2048
#define NH 16
#define DH 128
#define RR 64
#define MM (BB*SS)   /* 4096 */

// ---------------- scratch (device globals; no allocation) ----------------
static __device__ float g_wq[DD*RR];
static __device__ float g_wk[DD*RR];
static __device__ float g_wv[DD*RR];
static __device__ float g_wo[DD*RR];
static __device__ float g_resq[MM*RR];
static __device__ float g_resk[MM*RR];
static __device__ float g_resv[MM*RR];
static __device__ float g_q[(size_t)MM*DD];
static __device__ float g_k[(size_t)MM*DD];
static __device__ float g_v[(size_t)MM*DD];
static __device__ float g_ao[(size_t)MM*DD];

// ---------------- tf32 helpers ----------------
__device__ __forceinline__ uint32_t f2tf32(float x) {
    uint32_t r; asm("cvt.rna.tf32.f32 %0, %1;" : "=r"(r) : "f"(x)); return r;
}
// split x into hi (tf32) + lo (tf32 of residual); hi+lo ~= x to ~21 bits
__device__ __forceinline__ void tf32_split(float x, uint32_t& hi, uint32_t& lo) {
    hi = f2tf32(x);
    lo = f2tf32(x - __uint_as_float(hi));
}
__device__ __forceinline__ void mma_tf32(float4& c, const uint32_t* a,
                                         uint32_t b0, uint32_t b1) {
    asm volatile(
        "mma.sync.aligned.m16n8k8.row.col.f32.tf32.tf32.f32 "
        "{%0,%1,%2,%3}, {%4,%5,%6,%7}, {%8,%9}, {%0,%1,%2,%3};\n"
        : "+f"(c.x), "+f"(c.y), "+f"(c.z), "+f"(c.w)
        : "r"(a[0]), "r"(a[1]), "r"(a[2]), "r"(a[3]), "r"(b0), "r"(b1));
}

// ---------------- w = amp * cos(phase) ----------------
__global__ void wcos_kernel(const float* __restrict__ amp,
                            const float* __restrict__ phase,
                            float* __restrict__ w) {
    int i = blockIdx.x * 256 + threadIdx.x;
    w[i] = amp[i] * cosf(phase[i]);
}

// ---------------- fused QKV resonance GEMM ----------------
__global__ __launch_bounds__(256) void gemm_res_qkv(const float* __restrict__ X,
                                                    const float* __restrict__ BasQ,
                                                    const float* __restrict__ BasK,
                                                    const float* __restrict__ BasV,
                                                    float* __restrict__ outQ,
                                                    float* __restrict__ outK,
                                                    float* __restrict__ outV) {
    __shared__ float As[64][36];
    __shared__ float Bq[64][36];
    __shared__ float Bk[64][36];
    __shared__ float Bv[64][36];
    int tid = threadIdx.x;
    int tx = tid & 15, ty = tid >> 4;
    int m0 = blockIdx.x * 64;

    float aq[4][4] = {}, ak[4][4] = {}, av[4][4] = {};

    for (int kk = 0; kk < DD; kk += 32) {
        #pragma unroll
        for (int t = tid; t < 512; t += 256) {
            int r = t >> 3, c4 = t & 7;
            float4 v = *reinterpret_cast<const float4*>(&X[(size_t)(m0 + r) * DD + kk + c4 * 4]);
            As[r][c4*4+0] = v.x; As[r][c4*4+1] = v.y; As[r][c4*4+2] = v.z; As[r][c4*4+3] = v.w;
            float4 q4 = *reinterpret_cast<const float4*>(&BasQ[(size_t)r * DD + kk + c4 * 4]);
            Bq[r][c4*4+0] = q4.x; Bq[r][c4*4+1] = q4.y; Bq[r][c4*4+2] = q4.z; Bq[r][c4*4+3] = q4.w;
            float4 k4 = *reinterpret_cast<const float4*>(&BasK[(size_t)r * DD + kk + c4 * 4]);
            Bk[r][c4*4+0] = k4.x; Bk[r][c4*4+1] = k4.y; Bk[r][c4*4+2] = k4.z; Bk[r][c4*4+3] = k4.w;
            float4 v4 = *reinterpret_cast<const float4*>(&BasV[(size_t)r * DD + kk + c4 * 4]);
            Bv[r][c4*4+0] = v4.x; Bv[r][c4*4+1] = v4.y; Bv[r][c4*4+2] = v4.z; Bv[r][c4*4+3] = v4.w;
        }
        __syncthreads();
        #pragma unroll
        for (int k = 0; k < 32; k += 4) {
            float4 a[4];
            #pragma unroll
            for (int i = 0; i < 4; i++) a[i] = *reinterpret_cast<const float4*>(&As[ty*4+i][k]);
            float4 b[4];
            #pragma unroll
            for (int j = 0; j < 4; j++) b[j] = *reinterpret_cast<const float4*>(&Bq[tx*4+j][k]);
            #pragma unroll
            for (int i = 0; i < 4; i++)
                #pragma unroll
                for (int j = 0; j < 4; j++)
                    aq[i][j] += a[i].x*b[j].x + a[i].y*b[j].y + a[i].z*b[j].z + a[i].w*b[j].w;
            #pragma unroll
            for (int j = 0; j < 4; j++) b[j] = *reinterpret_cast<const float4*>(&Bk[tx*4+j][k]);
            #pragma unroll
            for (int i = 0; i < 4; i++)
                #pragma unroll
                for (int j = 0; j < 4; j++)
                    ak[i][j] += a[i].x*b[j].x + a[i].y*b[j].y + a[i].z*b[j].z + a[i].w*b[j].w;
            #pragma unroll
            for (int j = 0; j < 4; j++) b[j] = *reinterpret_cast<const float4*>(&Bv[tx*4+j][k]);
            #pragma unroll
            for (int i = 0; i < 4; i++)
                #pragma unroll
                for (int j = 0; j < 4; j++)
                    av[i][j] += a[i].x*b[j].x + a[i].y*b[j].y + a[i].z*b[j].z + a[i].w*b[j].w;
        }
        __syncthreads();
    }
    #pragma unroll
    for (int i = 0; i < 4; i++)
        #pragma unroll
        for (int j = 0; j < 4; j++) {
            size_t o = (size_t)(m0 + ty*4 + i) * RR + tx*4 + j;
            outQ[o] = aq[i][j];
            outK[o] = ak[i][j];
            outV[o] = av[i][j];
        }
}

// ---------------- single resonance GEMM (for O projection) ----------------
__global__ __launch_bounds__(256) void gemm_res(const float* __restrict__ X,
                                                const float* __restrict__ Bas,
                                                float* __restrict__ out) {
    __shared__ float As[64][36];
    __shared__ float Bs[64][36];
    int tid = threadIdx.x;
    int tx = tid & 15, ty = tid >> 4;
    int m0 = blockIdx.x * 64;

    float acc[4][4] = {};

    for (int kk = 0; kk < DD; kk += 32) {
        #pragma unroll
        for (int t = tid; t < 512; t += 256) {
            int r = t >> 3, c4 = t & 7;
            float4 v = *reinterpret_cast<const float4*>(&X[(size_t)(m0 + r) * DD + kk + c4 * 4]);
            As[r][c4*4+0] = v.x; As[r][c4*4+1] = v.y; As[r][c4*4+2] = v.z; As[r][c4*4+3] = v.w;
        }
        #pragma unroll
        for (int t = tid; t < 512; t += 256) {
            int r = t >> 3, c4 = t & 7;
            float4 v = *reinterpret_cast<const float4*>(&Bas[(size_t)r * DD + kk + c4 * 4]);
            Bs[r][c4*4+0] = v.x; Bs[r][c4*4+1] = v.y; Bs[r][c4*4+2] = v.z; Bs[r][c4*4+3] = v.w;
        }
        __syncthreads();
        #pragma unroll
        for (int k = 0; k < 32; k += 4) {
            float4 a[4], b[4];
            #pragma unroll
            for (int i = 0; i < 4; i++) a[i] = *reinterpret_cast<const float4*>(&As[ty*4+i][k]);
            #pragma unroll
            for (int j = 0; j < 4; j++) b[j] = *reinterpret_cast<const float4*>(&Bs[tx*4+j][k]);
            #pragma unroll
            for (int i = 0; i < 4; i++)
                #pragma unroll
                for (int j = 0; j < 4; j++)
                    acc[i][j] += a[i].x*b[j].x + a[i].y*b[j].y + a[i].z*b[j].z + a[i].w*b[j].w;
        }
        __syncthreads();
    }
    #pragma unroll
    for (int i = 0; i < 4; i++)
        #pragma unroll
        for (int j = 0; j < 4; j++)
            out[(size_t)(m0 + ty*4 + i) * RR + tx*4 + j] = acc[i][j];
}

// ---------------- expand GEMM ----------------
__global__ __launch_bounds__(256) void gemm_expand(const float* __restrict__ res,
                                                   const float* __restrict__ w,
                                                   float* __restrict__ out) {
    __shared__ float As[64][68];
    __shared__ float Bs[64][68];
    int tid = threadIdx.x;
    int tx = tid & 15, ty = tid >> 4;
    int m0 = blockIdx.x * 64;
    int n0 = blockIdx.y * 64;

    #pragma unroll
    for (int t = tid; t < 1024; t += 256) {
        int r = t >> 4, c4 = t & 15;
        float4 v = *reinterpret_cast<const float4*>(&res[(size_t)(m0 + r) * RR + c4 * 4]);
        As[r][c4*4+0] = v.x; As[r][c4*4+1] = v.y; As[r][c4*4+2] = v.z; As[r][c4*4+3] = v.w;
    }
    #pragma unroll
    for (int t = tid; t < 1024; t += 256) {
        int r = t >> 4, c4 = t & 15;
        float4 v = *reinterpret_cast<const float4*>(&w[(size_t)(n0 + r) * RR + c4 * 4]);
        Bs[r][c4*4+0] = v.x; Bs[r][c4*4+1] = v.y; Bs[r][c4*4+2] = v.z; Bs[r][c4*4+3] = v.w;
    }
    __syncthreads();

    float acc[4][4] = {};
    #pragma unroll
    for (int k = 0; k < 64; k += 4) {
        float4 a[4], b[4];
        #pragma unroll
        for (int i = 0; i < 4; i++) a[i] = *reinterpret_cast<const float4*>(&As[ty*4+i][k]);
        #pragma unroll
        for (int j = 0; j < 4; j++) b[j] = *reinterpret_cast<const float4*>(&Bs[tx*4+j][k]);
        #pragma unroll
        for (int i = 0; i < 4; i++)
            #pragma unroll
            for (int j = 0; j < 4; j++)
                acc[i][j] += a[i].x*b[j].x + a[i].y*b[j].y + a[i].z*b[j].z + a[i].w*b[j].w;
    }
    #pragma unroll
    for (int i = 0; i < 4; i++)
        #pragma unroll
        for (int j = 0; j < 4; j++)
            out[(size_t)(m0 + ty*4 + i) * DD + n0 + tx*4 + j] = acc[i][j];
}

// ---------------- flash attention (3xTF32 tensor-core mma, fp32 softmax) ----
// BM=128 queries/CTA, BN=64 keys/iter, 8 warps; warp w owns rows w*16..w*16+15.
// smem holds RAW fp32; hi/lo tf32 split happens at fragment load.
#define QPAD 132
#define KPAD 132
#define VPAD 136
#define PPAD 68
#define SM_QO 0
#define SM_KO (128*QPAD)
#define SM_VO (SM_KO + 64*KPAD)
#define SM_PO (SM_VO + 64*VPAD)
#define ATTN_SMEM_BYTES ((SM_PO + 128*PPAD) * 4)

__global__ __launch_bounds__(256, 1) void attn_kernel() {
    extern __shared__ float sm[];
    float* Qs = sm + SM_QO;
    float* Ks = sm + SM_KO;
    float* Vs = sm + SM_VO;
    float* Ps = sm + SM_PO;

    int tid = threadIdx.x;
    int wid = tid >> 5, lane = tid & 31;
    int g = lane >> 2, t4 = lane & 3;
    int qt = blockIdx.x, h = blockIdx.y, bz = blockIdx.z;
    const float scale = 0.08838834764831845f;  // 1/sqrt(128)
    int m0w = wid * 16;

    // ---- load Q tile 128x128 (raw fp32) ----
    const float* qbase = g_q + (size_t)(bz*SS + qt*128)*DD + h*DH;
    for (int t = tid; t < 4096; t += 256) {
        int r = t >> 5, c4 = t & 31;
        *reinterpret_cast<float4*>(&Qs[r*QPAD + c4*4]) =
            *reinterpret_cast<const float4*>(&qbase[(size_t)r*DD + c4*4]);
    }

    float4 oacc[16];
    #pragma unroll
    for (int i = 0; i < 16; i++) oacc[i] = make_float4(0.f,0.f,0.f,0.f);
    float mr0 = -INFINITY, mr1 = -INFINITY, lr0 = 0.f, lr1 = 0.f;

    for (int jt = 0; jt < 32; jt++) {
        __syncthreads();   // prior iteration's mma reads done
        const float* kb = g_k + (size_t)(bz*SS + jt*64)*DD + h*DH;
        const float* vb = g_v + (size_t)(bz*SS + jt*64)*DD + h*DH;
        for (int t = tid; t < 2048; t += 256) {
            int r = t >> 5, c4 = t & 31;
            *reinterpret_cast<float4*>(&Ks[r*KPAD + c4*4]) =
                *reinterpret_cast<const float4*>(&kb[(size_t)r*DD + c4*4]);
            *reinterpret_cast<float4*>(&Vs[r*VPAD + c4*4]) =
                *reinterpret_cast<const float4*>(&vb[(size_t)r*DD + c4*4]);
        }
        __syncthreads();

        // ---- S = Q @ K^T : warp tile 16x64, 3xTF32 compensated ----
        float4 sc[8];
        #pragma unroll
        for (int i = 0; i < 8; i++) sc[i] = make_float4(0.f,0.f,0.f,0.f);
        #pragma unroll 2
        for (int ks = 0; ks < 16; ks++) {
            const float* qp = &Qs[(m0w + g)*QPAD + ks*8 + t4];
            float af[4];
            af[0] = qp[0]; af[1] = qp[8*QPAD]; af[2] = qp[4]; af[3] = qp[8*QPAD + 4];
            uint32_t ah[4], al[4];
            #pragma unroll
            for (int i = 0; i < 4; i++) tf32_split(af[i], ah[i], al[i]);
            #pragma unroll
            for (int nt = 0; nt < 8; nt++) {
                const float* kp = &Ks[(nt*8 + g)*KPAD + ks*8 + t4];
                float b0f = kp[0], b1f = kp[4];
                uint32_t bh0, bl0, bh1, bl1;
                tf32_split(b0f, bh0, bl0);
                tf32_split(b1f, bh1, bl1);
                mma_tf32(sc[nt], ah, bh0, bh1);
                mma_tf32(sc[nt], ah, bl0, bl1);
                mma_tf32(sc[nt], al, bh0, bh1);
            }
        }

        // ---- online softmax (rows m0w+g and m0w+g+8) ----
        float mx0 = -INFINITY, mx1 = -INFINITY;
        #pragma unroll
        for (int nt = 0; nt < 8; nt++) {
            mx0 = fmaxf(mx0, fmaxf(sc[nt].x, sc[nt].y));
            mx1 = fmaxf(mx1, fmaxf(sc[nt].z, sc[nt].w));
        }
        mx0 *= scale; mx1 *= scale;
        mx0 = fmaxf(mx0, __shfl_xor_sync(0xffffffffu, mx0, 1));
        mx0 = fmaxf(mx0, __shfl_xor_sync(0xffffffffu, mx0, 2));
        mx1 = fmaxf(mx1, __shfl_xor_sync(0xffffffffu, mx1, 1));
        mx1 = fmaxf(mx1, __shfl_xor_sync(0xffffffffu, mx1, 2));
        float mn0 = fmaxf(mr0, mx0), mn1 = fmaxf(mr1, mx1);
        float ps0 = 0.f, ps1 = 0.f;
        #pragma unroll
        for (int nt = 0; nt < 8; nt++) {
            sc[nt].x = __expf(sc[nt].x*scale - mn0);
            sc[nt].y = __expf(sc[nt].y*scale - mn0);
            sc[nt].z = __expf(sc[nt].z*scale - mn1);
            sc[nt].w = __expf(sc[nt].w*scale - mn1);
            ps0 += sc[nt].x + sc[nt].y;
            ps1 += sc[nt].z + sc[nt].w;
            *reinterpret_cast<float2*>(&Ps[(m0w + g)*PPAD + nt*8 + 2*t4]) =
                make_float2(sc[nt].x, sc[nt].y);
            *reinterpret_cast<float2*>(&Ps[(m0w + g + 8)*PPAD + nt*8 + 2*t4]) =
                make_float2(sc[nt].z, sc[nt].w);
        }
        ps0 += __shfl_xor_sync(0xffffffffu, ps0, 1);
        ps0 += __shfl_xor_sync(0xffffffffu, ps0, 2);
        ps1 += __shfl_xor_sync(0xffffffffu, ps1, 1);
        ps1 += __shfl_xor_sync(0xffffffffu, ps1, 2);
        float al0 = __expf(mr0 - mn0), al1 = __expf(mr1 - mn1);
        lr0 = lr0*al0 + ps0; lr1 = lr1*al1 + ps1;
        mr0 = mn0; mr1 = mn1;
        #pragma unroll
        for (int i = 0; i < 16; i++) {
            oacc[i].x *= al0; oacc[i].y *= al0;
            oacc[i].z *= al1; oacc[i].w *= al1;
        }
        __syncwarp();   // P tile (warp-private rows) visible to all lanes

        // ---- O += P @ V : warp tile 16x128, 3xTF32 compensated ----
        #pragma unroll 2
        for (int ks = 0; ks < 8; ks++) {
            const float* pp = &Ps[(m0w + g)*PPAD + ks*8 + t4];
            float af[4];
            af[0] = pp[0]; af[1] = pp[8*PPAD]; af[2] = pp[4]; af[3] = pp[8*PPAD + 4];
            uint32_t ah[4], al[4];
            #pragma unroll
            for (int i = 0; i < 4; i++) tf32_split(af[i], ah[i], al[i]);
            #pragma unroll
            for (int nt = 0; nt < 16; nt++) {
                const float* vp = &Vs[(ks*8 + t4)*VPAD + nt*8 + g];
                float b0f = vp[0], b1f = vp[4*VPAD];
                uint32_t bh0, bl0, bh1, bl1;
                tf32_split(b0f, bh0, bl0);
                tf32_split(b1f, bh1, bl1);
                mma_tf32(oacc[nt], ah, bh0, bh1);
                mma_tf32(oacc[nt], ah, bl0, bl1);
                mma_tf32(oacc[nt], al, bh0, bh1);
            }
        }
    }

    // ---- epilogue ----
    float inv0 = 1.f/lr0, inv1 = 1.f/lr1;
    size_t row0 = (size_t)(bz*SS + qt*128 + m0w + g);
    float* ob0 = g_ao + row0*DD + h*DH;
    float* ob1 = ob0 + (size_t)8*DD;
    #pragma unroll
    for (int nt = 0; nt < 16; nt++) {
        int c = nt*8 + 2*t4;
        *reinterpret_cast<float2*>(&ob0[c]) = make_float2(oacc[nt].x*inv0, oacc[nt].y*inv0);
        *reinterpret_cast<float2*>(&ob1[c]) = make_float2(oacc[nt].z*inv1, oacc[nt].w*inv1);
    }
}

// ---------------- launch ----------------
extern "C" void kernel_launch(void* const* d_in, const int* in_sizes, int n_in,
                              void* d_out, int out_size) {
    const float* x       = (const float*)d_in[0];
    const float* basis_q = (const float*)d_in[1];
    const float* phase_q = (const float*)d_in[2];
    const float* amp_q   = (const float*)d_in[3];
    const float* basis_k = (const float*)d_in[4];
    const float* phase_k = (const float*)d_in[5];
    const float* amp_k   = (const float*)d_in[6];
    const float* basis_v = (const float*)d_in[7];
    const float* phase_v = (const float*)d_in[8];
    const float* amp_v   = (const float*)d_in[9];
    const float* basis_o = (const float*)d_in[10];
    const float* phase_o = (const float*)d_in[11];
    const float* amp_o   = (const float*)d_in[12];
    float* out = (float*)d_out;

    float *wq, *wk, *wv, *wo, *resq, *resk, *resv, *q, *k, *v, *ao;
    cudaGetSymbolAddress((void**)&wq, g_wq);
    cudaGetSymbolAddress((void**)&wk, g_wk);
    cudaGetSymbolAddress((void**)&wv, g_wv);
    cudaGetSymbolAddress((void**)&wo, g_wo);
    cudaGetSymbolAddress((void**)&resq, g_resq);
    cudaGetSymbolAddress((void**)&resk, g_resk);
    cudaGetSymbolAddress((void**)&resv, g_resv);
    cudaGetSymbolAddress((void**)&q, g_q);
    cudaGetSymbolAddress((void**)&k, g_k);
    cudaGetSymbolAddress((void**)&v, g_v);
    cudaGetSymbolAddress((void**)&ao, g_ao);

    cudaFuncSetAttribute(attn_kernel, cudaFuncAttributeMaxDynamicSharedMemorySize,
                         ATTN_SMEM_BYTES);

    // weights
    wcos_kernel<<<512, 256>>>(amp_q, phase_q, wq);
    wcos_kernel<<<512, 256>>>(amp_k, phase_k, wk);
    wcos_kernel<<<512, 256>>>(amp_v, phase_v, wv);
    wcos_kernel<<<512, 256>>>(amp_o, phase_o, wo);

    // fused q/k/v resonance, then expansions
    gemm_res_qkv<<<64, 256>>>(x, basis_q, basis_k, basis_v, resq, resk, resv);
    gemm_expand<<<dim3(64, 32), 256>>>(resq, wq, q);
    gemm_expand<<<dim3(64, 32), 256>>>(resk, wk, k);
    gemm_expand<<<dim3(64, 32), 256>>>(resv, wv, v);

    // attention (3xTF32 tensor cores)
    attn_kernel<<<dim3(16, NH, BB), 256, ATTN_SMEM_BYTES>>>();

    // output projection
    gemm_res<<<64, 256>>>(ao, basis_o, resq);
    gemm_expand<<<dim3(64, 32), 256>>>(resq, wo, out);
}

// round 7
// speedup vs baseline: 2.3918x; 1.4156x over previous
#include <cuda_runtime.h>
#include <cuda_bf16.h>
#include <math.h>
#include <stdint.h>

#define BB 2
#define SS 2048
#define DD 2048
#define NH 16
#define DH 128
#define RR 64
#define MM (BB*SS)   /* 4096 */

// ---------------- scratch (device globals; no allocation) ----------------
static __device__ float g_wq[DD*RR];
static __device__ float g_wk[DD*RR];
static __device__ float g_wv[DD*RR];
static __device__ float g_wo[DD*RR];
static __device__ float g_resq[MM*RR];
static __device__ float g_resk[MM*RR];
static __device__ float g_resv[MM*RR];
static __device__ float g_ao[(size_t)MM*DD];
// split bf16 operands for attention
static __device__ __nv_bfloat16 g_qhi[(size_t)MM*DD];
static __device__ __nv_bfloat16 g_qlo[(size_t)MM*DD];
static __device__ __nv_bfloat16 g_khi[(size_t)MM*DD];
static __device__ __nv_bfloat16 g_klo[(size_t)MM*DD];
static __device__ __nv_bfloat16 g_vthi[(size_t)MM*DD];  // [b][h][d][s]
static __device__ __nv_bfloat16 g_vtlo[(size_t)MM*DD];

// ---------------- mma helper ----------------
__device__ __forceinline__ void mma_bf16(float4& c, const uint32_t* a,
                                         uint32_t b0, uint32_t b1) {
    asm volatile(
        "mma.sync.aligned.m16n8k16.row.col.f32.bf16.bf16.f32 "
        "{%0,%1,%2,%3}, {%4,%5,%6,%7}, {%8,%9}, {%0,%1,%2,%3};\n"
        : "+f"(c.x), "+f"(c.y), "+f"(c.z), "+f"(c.w)
        : "r"(a[0]), "r"(a[1]), "r"(a[2]), "r"(a[3]), "r"(b0), "r"(b1));
}

// split two floats into packed bf16x2 hi and lo
__device__ __forceinline__ void bf16_split2(float v0, float v1,
                                            uint32_t& hi, uint32_t& lo) {
    __nv_bfloat162 h2 = __floats2bfloat162_rn(v0, v1);
    float2 hf = __bfloat1622float2(h2);
    __nv_bfloat162 l2 = __floats2bfloat162_rn(v0 - hf.x, v1 - hf.y);
    hi = *reinterpret_cast<uint32_t*>(&h2);
    lo = *reinterpret_cast<uint32_t*>(&l2);
}

// ---------------- w = amp * cos(phase) ----------------
__global__ void wcos_kernel(const float* __restrict__ amp,
                            const float* __restrict__ phase,
                            float* __restrict__ w) {
    int i = blockIdx.x * 256 + threadIdx.x;
    w[i] = amp[i] * cosf(phase[i]);
}

// ---------------- fused QKV resonance GEMM ----------------
__global__ __launch_bounds__(256) void gemm_res_qkv(const float* __restrict__ X,
                                                    const float* __restrict__ BasQ,
                                                    const float* __restrict__ BasK,
                                                    const float* __restrict__ BasV,
                                                    float* __restrict__ outQ,
                                                    float* __restrict__ outK,
                                                    float* __restrict__ outV) {
    __shared__ float As[64][36];
    __shared__ float Bq[64][36];
    __shared__ float Bk[64][36];
    __shared__ float Bv[64][36];
    int tid = threadIdx.x;
    int tx = tid & 15, ty = tid >> 4;
    int m0 = blockIdx.x * 64;

    float aq[4][4] = {}, ak[4][4] = {}, av[4][4] = {};

    for (int kk = 0; kk < DD; kk += 32) {
        #pragma unroll
        for (int t = tid; t < 512; t += 256) {
            int r = t >> 3, c4 = t & 7;
            float4 v = *reinterpret_cast<const float4*>(&X[(size_t)(m0 + r) * DD + kk + c4 * 4]);
            As[r][c4*4+0] = v.x; As[r][c4*4+1] = v.y; As[r][c4*4+2] = v.z; As[r][c4*4+3] = v.w;
            float4 q4 = *reinterpret_cast<const float4*>(&BasQ[(size_t)r * DD + kk + c4 * 4]);
            Bq[r][c4*4+0] = q4.x; Bq[r][c4*4+1] = q4.y; Bq[r][c4*4+2] = q4.z; Bq[r][c4*4+3] = q4.w;
            float4 k4 = *reinterpret_cast<const float4*>(&BasK[(size_t)r * DD + kk + c4 * 4]);
            Bk[r][c4*4+0] = k4.x; Bk[r][c4*4+1] = k4.y; Bk[r][c4*4+2] = k4.z; Bk[r][c4*4+3] = k4.w;
            float4 v4 = *reinterpret_cast<const float4*>(&BasV[(size_t)r * DD + kk + c4 * 4]);
            Bv[r][c4*4+0] = v4.x; Bv[r][c4*4+1] = v4.y; Bv[r][c4*4+2] = v4.z; Bv[r][c4*4+3] = v4.w;
        }
        __syncthreads();
        #pragma unroll
        for (int k = 0; k < 32; k += 4) {
            float4 a[4];
            #pragma unroll
            for (int i = 0; i < 4; i++) a[i] = *reinterpret_cast<const float4*>(&As[ty*4+i][k]);
            float4 b[4];
            #pragma unroll
            for (int j = 0; j < 4; j++) b[j] = *reinterpret_cast<const float4*>(&Bq[tx*4+j][k]);
            #pragma unroll
            for (int i = 0; i < 4; i++)
                #pragma unroll
                for (int j = 0; j < 4; j++)
                    aq[i][j] += a[i].x*b[j].x + a[i].y*b[j].y + a[i].z*b[j].z + a[i].w*b[j].w;
            #pragma unroll
            for (int j = 0; j < 4; j++) b[j] = *reinterpret_cast<const float4*>(&Bk[tx*4+j][k]);
            #pragma unroll
            for (int i = 0; i < 4; i++)
                #pragma unroll
                for (int j = 0; j < 4; j++)
                    ak[i][j] += a[i].x*b[j].x + a[i].y*b[j].y + a[i].z*b[j].z + a[i].w*b[j].w;
            #pragma unroll
            for (int j = 0; j < 4; j++) b[j] = *reinterpret_cast<const float4*>(&Bv[tx*4+j][k]);
            #pragma unroll
            for (int i = 0; i < 4; i++)
                #pragma unroll
                for (int j = 0; j < 4; j++)
                    av[i][j] += a[i].x*b[j].x + a[i].y*b[j].y + a[i].z*b[j].z + a[i].w*b[j].w;
        }
        __syncthreads();
    }
    #pragma unroll
    for (int i = 0; i < 4; i++)
        #pragma unroll
        for (int j = 0; j < 4; j++) {
            size_t o = (size_t)(m0 + ty*4 + i) * RR + tx*4 + j;
            outQ[o] = aq[i][j];
            outK[o] = ak[i][j];
            outV[o] = av[i][j];
        }
}

// ---------------- single resonance GEMM (for O projection) ----------------
__global__ __launch_bounds__(256) void gemm_res(const float* __restrict__ X,
                                                const float* __restrict__ Bas,
                                                float* __restrict__ out) {
    __shared__ float As[64][36];
    __shared__ float Bs[64][36];
    int tid = threadIdx.x;
    int tx = tid & 15, ty = tid >> 4;
    int m0 = blockIdx.x * 64;

    float acc[4][4] = {};

    for (int kk = 0; kk < DD; kk += 32) {
        #pragma unroll
        for (int t = tid; t < 512; t += 256) {
            int r = t >> 3, c4 = t & 7;
            float4 v = *reinterpret_cast<const float4*>(&X[(size_t)(m0 + r) * DD + kk + c4 * 4]);
            As[r][c4*4+0] = v.x; As[r][c4*4+1] = v.y; As[r][c4*4+2] = v.z; As[r][c4*4+3] = v.w;
        }
        #pragma unroll
        for (int t = tid; t < 512; t += 256) {
            int r = t >> 3, c4 = t & 7;
            float4 v = *reinterpret_cast<const float4*>(&Bas[(size_t)r * DD + kk + c4 * 4]);
            Bs[r][c4*4+0] = v.x; Bs[r][c4*4+1] = v.y; Bs[r][c4*4+2] = v.z; Bs[r][c4*4+3] = v.w;
        }
        __syncthreads();
        #pragma unroll
        for (int k = 0; k < 32; k += 4) {
            float4 a[4], b[4];
            #pragma unroll
            for (int i = 0; i < 4; i++) a[i] = *reinterpret_cast<const float4*>(&As[ty*4+i][k]);
            #pragma unroll
            for (int j = 0; j < 4; j++) b[j] = *reinterpret_cast<const float4*>(&Bs[tx*4+j][k]);
            #pragma unroll
            for (int i = 0; i < 4; i++)
                #pragma unroll
                for (int j = 0; j < 4; j++)
                    acc[i][j] += a[i].x*b[j].x + a[i].y*b[j].y + a[i].z*b[j].z + a[i].w*b[j].w;
        }
        __syncthreads();
    }
    #pragma unroll
    for (int i = 0; i < 4; i++)
        #pragma unroll
        for (int j = 0; j < 4; j++)
            out[(size_t)(m0 + ty*4 + i) * RR + tx*4 + j] = acc[i][j];
}

// ---------------- expand GEMM (fp32 out, for final O projection) -----------
__global__ __launch_bounds__(256) void gemm_expand(const float* __restrict__ res,
                                                   const float* __restrict__ w,
                                                   float* __restrict__ out) {
    __shared__ float As[64][68];
    __shared__ float Bs[64][68];
    int tid = threadIdx.x;
    int tx = tid & 15, ty = tid >> 4;
    int m0 = blockIdx.x * 64;
    int n0 = blockIdx.y * 64;

    #pragma unroll
    for (int t = tid; t < 1024; t += 256) {
        int r = t >> 4, c4 = t & 15;
        float4 v = *reinterpret_cast<const float4*>(&res[(size_t)(m0 + r) * RR + c4 * 4]);
        As[r][c4*4+0] = v.x; As[r][c4*4+1] = v.y; As[r][c4*4+2] = v.z; As[r][c4*4+3] = v.w;
        float4 wv = *reinterpret_cast<const float4*>(&w[(size_t)(n0 + r) * RR + c4 * 4]);
        Bs[r][c4*4+0] = wv.x; Bs[r][c4*4+1] = wv.y; Bs[r][c4*4+2] = wv.z; Bs[r][c4*4+3] = wv.w;
    }
    __syncthreads();

    float acc[4][4] = {};
    #pragma unroll
    for (int k = 0; k < 64; k += 4) {
        float4 a[4], b[4];
        #pragma unroll
        for (int i = 0; i < 4; i++) a[i] = *reinterpret_cast<const float4*>(&As[ty*4+i][k]);
        #pragma unroll
        for (int j = 0; j < 4; j++) b[j] = *reinterpret_cast<const float4*>(&Bs[tx*4+j][k]);
        #pragma unroll
        for (int i = 0; i < 4; i++)
            #pragma unroll
            for (int j = 0; j < 4; j++)
                acc[i][j] += a[i].x*b[j].x + a[i].y*b[j].y + a[i].z*b[j].z + a[i].w*b[j].w;
    }
    #pragma unroll
    for (int i = 0; i < 4; i++)
        #pragma unroll
        for (int j = 0; j < 4; j++)
            out[(size_t)(m0 + ty*4 + i) * DD + n0 + tx*4 + j] = acc[i][j];
}

// ---------------- expand GEMM with bf16 hi/lo split output (Q, K) ----------
__global__ __launch_bounds__(256) void gemm_expand_qk(const float* __restrict__ res,
                                                      const float* __restrict__ w,
                                                      __nv_bfloat16* __restrict__ ohi,
                                                      __nv_bfloat16* __restrict__ olo) {
    __shared__ float As[64][68];
    __shared__ float Bs[64][68];
    int tid = threadIdx.x;
    int tx = tid & 15, ty = tid >> 4;
    int m0 = blockIdx.x * 64;
    int n0 = blockIdx.y * 64;

    #pragma unroll
    for (int t = tid; t < 1024; t += 256) {
        int r = t >> 4, c4 = t & 15;
        float4 v = *reinterpret_cast<const float4*>(&res[(size_t)(m0 + r) * RR + c4 * 4]);
        As[r][c4*4+0] = v.x; As[r][c4*4+1] = v.y; As[r][c4*4+2] = v.z; As[r][c4*4+3] = v.w;
        float4 wv = *reinterpret_cast<const float4*>(&w[(size_t)(n0 + r) * RR + c4 * 4]);
        Bs[r][c4*4+0] = wv.x; Bs[r][c4*4+1] = wv.y; Bs[r][c4*4+2] = wv.z; Bs[r][c4*4+3] = wv.w;
    }
    __syncthreads();

    float acc[4][4] = {};
    #pragma unroll
    for (int k = 0; k < 64; k += 4) {
        float4 a[4], b[4];
        #pragma unroll
        for (int i = 0; i < 4; i++) a[i] = *reinterpret_cast<const float4*>(&As[ty*4+i][k]);
        #pragma unroll
        for (int j = 0; j < 4; j++) b[j] = *reinterpret_cast<const float4*>(&Bs[tx*4+j][k]);
        #pragma unroll
        for (int i = 0; i < 4; i++)
            #pragma unroll
            for (int j = 0; j < 4; j++)
                acc[i][j] += a[i].x*b[j].x + a[i].y*b[j].y + a[i].z*b[j].z + a[i].w*b[j].w;
    }
    #pragma unroll
    for (int i = 0; i < 4; i++)
        #pragma unroll
        for (int j = 0; j < 4; j += 2) {
            uint32_t hp, lp;
            bf16_split2(acc[i][j], acc[i][j+1], hp, lp);
            size_t o = (size_t)(m0 + ty*4 + i) * DD + n0 + tx*4 + j;
            *reinterpret_cast<uint32_t*>(&ohi[o]) = hp;
            *reinterpret_cast<uint32_t*>(&olo[o]) = lp;
        }
}

// ---------------- expand GEMM for V: bf16 hi/lo, TRANSPOSED output ----------
// output layout: [b][h][d][s] so attention PV B-fragments are contiguous in k.
__global__ __launch_bounds__(256) void gemm_expand_vt(const float* __restrict__ res,
                                                      const float* __restrict__ w,
                                                      __nv_bfloat16* __restrict__ othi,
                                                      __nv_bfloat16* __restrict__ otlo) {
    __shared__ float As[64][68];
    __shared__ float Bs[64][68];
    int tid = threadIdx.x;
    int tx = tid & 15, ty = tid >> 4;
    int m0 = blockIdx.x * 64;
    int n0 = blockIdx.y * 64;

    #pragma unroll
    for (int t = tid; t < 1024; t += 256) {
        int r = t >> 4, c4 = t & 15;
        float4 v = *reinterpret_cast<const float4*>(&res[(size_t)(m0 + r) * RR + c4 * 4]);
        As[r][c4*4+0] = v.x; As[r][c4*4+1] = v.y; As[r][c4*4+2] = v.z; As[r][c4*4+3] = v.w;
        float4 wv = *reinterpret_cast<const float4*>(&w[(size_t)(n0 + r) * RR + c4 * 4]);
        Bs[r][c4*4+0] = wv.x; Bs[r][c4*4+1] = wv.y; Bs[r][c4*4+2] = wv.z; Bs[r][c4*4+3] = wv.w;
    }
    __syncthreads();

    float acc[4][4] = {};
    #pragma unroll
    for (int k = 0; k < 64; k += 4) {
        float4 a[4], b[4];
        #pragma unroll
        for (int i = 0; i < 4; i++) a[i] = *reinterpret_cast<const float4*>(&As[ty*4+i][k]);
        #pragma unroll
        for (int j = 0; j < 4; j++) b[j] = *reinterpret_cast<const float4*>(&Bs[tx*4+j][k]);
        #pragma unroll
        for (int i = 0; i < 4; i++)
            #pragma unroll
            for (int j = 0; j < 4; j++)
                acc[i][j] += a[i].x*b[j].x + a[i].y*b[j].y + a[i].z*b[j].z + a[i].w*b[j].w;
    }

    // stage transposed tile: Ss[n_local][m_local]
    __syncthreads();
    float (*Ss)[68] = As;
    #pragma unroll
    for (int i = 0; i < 4; i++)
        #pragma unroll
        for (int j = 0; j < 4; j++)
            Ss[tx*4 + j][ty*4 + i] = acc[i][j];
    __syncthreads();

    int b = m0 >> 11;            // m0 / SS
    int s0 = m0 & (SS - 1);
    int r = tid >> 2;            // n_local row 0..63
    int c8 = (tid & 3) * 16;     // 16 s-positions
    int ng = n0 + r;
    int h = ng >> 7, d = ng & 127;
    size_t base = ((size_t)(b * NH + h) * DH + d) * SS + s0 + c8;
    #pragma unroll
    for (int i = 0; i < 16; i += 2) {
        uint32_t hp, lp;
        bf16_split2(Ss[r][c8 + i], Ss[r][c8 + i + 1], hp, lp);
        *reinterpret_cast<uint32_t*>(&othi[base + i]) = hp;
        *reinterpret_cast<uint32_t*>(&otlo[base + i]) = lp;
    }
}

// ---------------- flash attention (compensated bf16 mma, fp32 softmax) -----
// BM=128 q/CTA, BN=64 keys/iter, 8 warps; warp w owns rows w*16..w*16+15.
// smem pitches (u32): Q 68, K 68, Vt 36, P 36 (all ≡4 mod 32 → conflict-free).
#define QP 68
#define KP 68
#define VP 36
#define PP 36
#define OFF_QH 0
#define OFF_QL (128*QP)                 /* 8704  */
#define OFF_KH (OFF_QL + 128*QP)        /* 17408 */
#define OFF_KL (OFF_KH + 64*KP)         /* 21760 */
#define OFF_VH (OFF_KL + 64*KP)         /* 26112 */
#define OFF_VL (OFF_VH + 128*VP)        /* 30720 */
#define OFF_PH (OFF_VL + 128*VP)        /* 35328 */
#define OFF_PL (OFF_PH + 128*PP)        /* 39936 */
#define ATTN_SMEM_U32 (OFF_PL + 128*PP) /* 44544 */
#define ATTN_SMEM_BYTES (ATTN_SMEM_U32 * 4)

__global__ __launch_bounds__(256, 1) void attn_kernel() {
    extern __shared__ uint32_t smu[];
    uint32_t* QH = smu + OFF_QH;
    uint32_t* QL = smu + OFF_QL;
    uint32_t* KH = smu + OFF_KH;
    uint32_t* KL = smu + OFF_KL;
    uint32_t* VH = smu + OFF_VH;
    uint32_t* VL = smu + OFF_VL;
    uint32_t* PH = smu + OFF_PH;
    uint32_t* PL = smu + OFF_PL;

    int tid = threadIdx.x;
    int wid = tid >> 5, lane = tid & 31;
    int g = lane >> 2, t4 = lane & 3;
    int qt = blockIdx.x, h = blockIdx.y, bz = blockIdx.z;
    const float scale = 0.08838834764831845f;  // 1/sqrt(128)
    int m0w = wid * 16;

    // ---- load Q tile 128x128 hi+lo (bf16, uint4 = 8 elems) ----
    size_t qoff = (size_t)(bz*SS + qt*128)*DD + h*DH;
    const uint4* qh4 = reinterpret_cast<const uint4*>(g_qhi + qoff);
    const uint4* ql4 = reinterpret_cast<const uint4*>(g_qlo + qoff);
    for (int t = tid; t < 2048; t += 256) {
        int r = t >> 4, c = t & 15;   // row 0..127, 16 uint4 per row
        *reinterpret_cast<uint4*>(&QH[r*QP + c*4]) = qh4[(size_t)r*256 + c];
        *reinterpret_cast<uint4*>(&QL[r*QP + c*4]) = ql4[(size_t)r*256 + c];
    }

    float4 oacc[16];
    #pragma unroll
    for (int i = 0; i < 16; i++) oacc[i] = make_float4(0.f,0.f,0.f,0.f);
    float mr0 = -INFINITY, mr1 = -INFINITY, lr0 = 0.f, lr1 = 0.f;

    size_t vtoff = ((size_t)(bz*NH + h) * DH) * SS;

    for (int jt = 0; jt < 32; jt++) {
        __syncthreads();   // prior iteration's mma reads done
        size_t koff = (size_t)(bz*SS + jt*64)*DD + h*DH;
        const uint4* kh4 = reinterpret_cast<const uint4*>(g_khi + koff);
        const uint4* kl4 = reinterpret_cast<const uint4*>(g_klo + koff);
        const uint4* vh4 = reinterpret_cast<const uint4*>(g_vthi + vtoff + jt*64);
        const uint4* vl4 = reinterpret_cast<const uint4*>(g_vtlo + vtoff + jt*64);
        for (int t = tid; t < 1024; t += 256) {
            int kr = t >> 4, kc = t & 15;     // K: 64 rows x 16 uint4
            *reinterpret_cast<uint4*>(&KH[kr*KP + kc*4]) = kh4[(size_t)kr*256 + kc];
            *reinterpret_cast<uint4*>(&KL[kr*KP + kc*4]) = kl4[(size_t)kr*256 + kc];
            int vr = t >> 3, vc = t & 7;      // Vt: 128 rows x 8 uint4
            *reinterpret_cast<uint4*>(&VH[vr*VP + vc*4]) = vh4[(size_t)vr*256 + vc];
            *reinterpret_cast<uint4*>(&VL[vr*VP + vc*4]) = vl4[(size_t)vr*256 + vc];
        }
        __syncthreads();

        // ---- S = Q @ K^T : warp tile 16x64, compensated bf16 ----
        float4 sc[8];
        #pragma unroll
        for (int i = 0; i < 8; i++) sc[i] = make_float4(0.f,0.f,0.f,0.f);
        #pragma unroll
        for (int ks = 0; ks < 8; ks++) {
            const uint32_t* qhp = &QH[(m0w + g)*QP + ks*8 + t4];
            const uint32_t* qlp = &QL[(m0w + g)*QP + ks*8 + t4];
            uint32_t ah[4] = { qhp[0], qhp[8*QP], qhp[4], qhp[8*QP + 4] };
            uint32_t al[4] = { qlp[0], qlp[8*QP], qlp[4], qlp[8*QP + 4] };
            #pragma unroll
            for (int nt = 0; nt < 8; nt++) {
                const uint32_t* khp = &KH[(nt*8 + g)*KP + ks*8 + t4];
                const uint32_t* klp = &KL[(nt*8 + g)*KP + ks*8 + t4];
                uint32_t bh0 = khp[0], bh1 = khp[4];
                uint32_t bl0 = klp[0], bl1 = klp[4];
                mma_bf16(sc[nt], ah, bh0, bh1);
                mma_bf16(sc[nt], ah, bl0, bl1);
                mma_bf16(sc[nt], al, bh0, bh1);
            }
        }

        // ---- online softmax (rows m0w+g and m0w+g+8) ----
        float mx0 = -INFINITY, mx1 = -INFINITY;
        #pragma unroll
        for (int nt = 0; nt < 8; nt++) {
            mx0 = fmaxf(mx0, fmaxf(sc[nt].x, sc[nt].y));
            mx1 = fmaxf(mx1, fmaxf(sc[nt].z, sc[nt].w));
        }
        mx0 *= scale; mx1 *= scale;
        mx0 = fmaxf(mx0, __shfl_xor_sync(0xffffffffu, mx0, 1));
        mx0 = fmaxf(mx0, __shfl_xor_sync(0xffffffffu, mx0, 2));
        mx1 = fmaxf(mx1, __shfl_xor_sync(0xffffffffu, mx1, 1));
        mx1 = fmaxf(mx1, __shfl_xor_sync(0xffffffffu, mx1, 2));
        float mn0 = fmaxf(mr0, mx0), mn1 = fmaxf(mr1, mx1);
        float ps0 = 0.f, ps1 = 0.f;
        #pragma unroll
        for (int nt = 0; nt < 8; nt++) {
            sc[nt].x = __expf(sc[nt].x*scale - mn0);
            sc[nt].y = __expf(sc[nt].y*scale - mn0);
            sc[nt].z = __expf(sc[nt].z*scale - mn1);
            sc[nt].w = __expf(sc[nt].w*scale - mn1);
            ps0 += sc[nt].x + sc[nt].y;
            ps1 += sc[nt].z + sc[nt].w;
            uint32_t hp, lp;
            bf16_split2(sc[nt].x, sc[nt].y, hp, lp);
            PH[(m0w + g)*PP + nt*4 + t4] = hp;
            PL[(m0w + g)*PP + nt*4 + t4] = lp;
            bf16_split2(sc[nt].z, sc[nt].w, hp, lp);
            PH[(m0w + g + 8)*PP + nt*4 + t4] = hp;
            PL[(m0w + g + 8)*PP + nt*4 + t4] = lp;
        }
        ps0 += __shfl_xor_sync(0xffffffffu, ps0, 1);
        ps0 += __shfl_xor_sync(0xffffffffu, ps0, 2);
        ps1 += __shfl_xor_sync(0xffffffffu, ps1, 1);
        ps1 += __shfl_xor_sync(0xffffffffu, ps1, 2);
        float al0 = __expf(mr0 - mn0), al1 = __expf(mr1 - mn1);
        lr0 = lr0*al0 + ps0; lr1 = lr1*al1 + ps1;
        mr0 = mn0; mr1 = mn1;
        #pragma unroll
        for (int i = 0; i < 16; i++) {
            oacc[i].x *= al0; oacc[i].y *= al0;
            oacc[i].z *= al1; oacc[i].w *= al1;
        }
        __syncwarp();   // P rows are warp-private

        // ---- O += P @ V : warp tile 16x128, compensated bf16 ----
        #pragma unroll
        for (int ks = 0; ks < 4; ks++) {
            const uint32_t* php = &PH[(m0w + g)*PP + ks*8 + t4];
            const uint32_t* plp = &PL[(m0w + g)*PP + ks*8 + t4];
            uint32_t ah[4] = { php[0], php[8*PP], php[4], php[8*PP + 4] };
            uint32_t al[4] = { plp[0], plp[8*PP], plp[4], plp[8*PP + 4] };
            #pragma unroll
            for (int nt = 0; nt < 16; nt++) {
                const uint32_t* vhp = &VH[(nt*8 + g)*VP + ks*8 + t4];
                const uint32_t* vlp = &VL[(nt*8 + g)*VP + ks*8 + t4];
                uint32_t bh0 = vhp[0], bh1 = vhp[4];
                uint32_t bl0 = vlp[0], bl1 = vlp[4];
                mma_bf16(oacc[nt], ah, bh0, bh1);
                mma_bf16(oacc[nt], ah, bl0, bl1);
                mma_bf16(oacc[nt], al, bh0, bh1);
            }
        }
    }

    // ---- epilogue ----
    float inv0 = 1.f/lr0, inv1 = 1.f/lr1;
    size_t row0 = (size_t)(bz*SS + qt*128 + m0w + g);
    float* ob0 = g_ao + row0*DD + h*DH;
    float* ob1 = ob0 + (size_t)8*DD;
    #pragma unroll
    for (int nt = 0; nt < 16; nt++) {
        int c = nt*8 + 2*t4;
        *reinterpret_cast<float2*>(&ob0[c]) = make_float2(oacc[nt].x*inv0, oacc[nt].y*inv0);
        *reinterpret_cast<float2*>(&ob1[c]) = make_float2(oacc[nt].z*inv1, oacc[nt].w*inv1);
    }
}

// ---------------- launch ----------------
extern "C" void kernel_launch(void* const* d_in, const int* in_sizes, int n_in,
                              void* d_out, int out_size) {
    const float* x       = (const float*)d_in[0];
    const float* basis_q = (const float*)d_in[1];
    const float* phase_q = (const float*)d_in[2];
    const float* amp_q   = (const float*)d_in[3];
    const float* basis_k = (const float*)d_in[4];
    const float* phase_k = (const float*)d_in[5];
    const float* amp_k   = (const float*)d_in[6];
    const float* basis_v = (const float*)d_in[7];
    const float* phase_v = (const float*)d_in[8];
    const float* amp_v   = (const float*)d_in[9];
    const float* basis_o = (const float*)d_in[10];
    const float* phase_o = (const float*)d_in[11];
    const float* amp_o   = (const float*)d_in[12];
    float* out = (float*)d_out;

    float *wq, *wk, *wv, *wo, *resq, *resk, *resv, *ao;
    __nv_bfloat16 *qhi, *qlo, *khi, *klo, *vthi, *vtlo;
    cudaGetSymbolAddress((void**)&wq, g_wq);
    cudaGetSymbolAddress((void**)&wk, g_wk);
    cudaGetSymbolAddress((void**)&wv, g_wv);
    cudaGetSymbolAddress((void**)&wo, g_wo);
    cudaGetSymbolAddress((void**)&resq, g_resq);
    cudaGetSymbolAddress((void**)&resk, g_resk);
    cudaGetSymbolAddress((void**)&resv, g_resv);
    cudaGetSymbolAddress((void**)&ao, g_ao);
    cudaGetSymbolAddress((void**)&qhi, g_qhi);
    cudaGetSymbolAddress((void**)&qlo, g_qlo);
    cudaGetSymbolAddress((void**)&khi, g_khi);
    cudaGetSymbolAddress((void**)&klo, g_klo);
    cudaGetSymbolAddress((void**)&vthi, g_vthi);
    cudaGetSymbolAddress((void**)&vtlo, g_vtlo);

    cudaFuncSetAttribute(attn_kernel, cudaFuncAttributeMaxDynamicSharedMemorySize,
                         ATTN_SMEM_BYTES);

    // weights
    wcos_kernel<<<512, 256>>>(amp_q, phase_q, wq);
    wcos_kernel<<<512, 256>>>(amp_k, phase_k, wk);
    wcos_kernel<<<512, 256>>>(amp_v, phase_v, wv);
    wcos_kernel<<<512, 256>>>(amp_o, phase_o, wo);

    // fused q/k/v resonance, then expansions (split bf16 outputs)
    gemm_res_qkv<<<64, 256>>>(x, basis_q, basis_k, basis_v, resq, resk, resv);
    gemm_expand_qk<<<dim3(64, 32), 256>>>(resq, wq, qhi, qlo);
    gemm_expand_qk<<<dim3(64, 32), 256>>>(resk, wk, khi, klo);
    gemm_expand_vt<<<dim3(64, 32), 256>>>(resv, wv, vthi, vtlo);

    // attention (compensated bf16 tensor cores)
    attn_kernel<<<dim3(16, NH, BB), 256, ATTN_SMEM_BYTES>>>();

    // output projection
    gemm_res<<<64, 256>>>(ao, basis_o, resq);
    gemm_expand<<<dim3(64, 32), 256>>>(resq, wo, out);
}